// round 3
// baseline (speedup 1.0000x reference)
#include <cuda_runtime.h>
#include <cstdint>

// PatchMerged fused: Haar-DWT2 + LayerNorm + (384->192) reduction GEMM
// out[b, h*128+w, d] = r*(G - mu*s[d]) + t[d],  G = patch @ W4 (tf32 mma)

__device__ float g_W[12 * 192 * 32];  // [kchunk][d][k_local], tf32-rounded
__device__ float g_s[192];
__device__ float g_t[192];

__device__ __forceinline__ float tf32r(float x) {
    float r; asm("cvt.rna.tf32.f32 %0, %1;" : "=f"(r) : "f"(x)); return r;
}

// W4[(c,q),d] = 0.5*( Wll + -+Wlh + -+Whl + -+Whh ),  W' = norm_w*w_red
__global__ void pm_prep_w(const float* __restrict__ nw, const float* __restrict__ wr) {
    int idx = blockIdx.x * 256 + threadIdx.x;
    if (idx >= 384 * 192) return;
    int k = idx / 192, d = idx - k * 192;
    int c = k >> 2, q = k & 3, dy = q >> 1, dx = q & 1;
    float wll = nw[c]         * wr[c * 192 + d];
    float wlh = nw[96 + c]    * wr[(96 + c) * 192 + d];
    float whl = nw[192 + c]   * wr[(192 + c) * 192 + d];
    float whh = nw[288 + c]   * wr[(288 + c) * 192 + d];
    float v = 0.5f * (wll + (dy ? -wlh : wlh) + (dx ? -whl : whl)
                          + ((dx ^ dy) ? -whh : whh));
    g_W[((k >> 5) * 192 + d) * 32 + (k & 31)] = tf32r(v);
}

__global__ void pm_prep_st(const float* __restrict__ nw, const float* __restrict__ nb,
                           const float* __restrict__ wr) {
    int d = threadIdx.x;
    if (d >= 192) return;
    float s = 0.f, t = 0.f;
    for (int yc = 0; yc < 384; ++yc) {
        float w = wr[yc * 192 + d];
        s += nw[yc] * w; t += nb[yc] * w;
    }
    g_s[d] = s; g_t[d] = t;
}

#define LOAD_A(ck) do {                                                           \
    const float* xp = x + xbase0 + (size_t)((ck) * 8 + c_local) * 65536;          \
    _Pragma("unroll") for (int i = 0; i < 4; i++)                                 \
    _Pragma("unroll") for (int dy = 0; dy < 2; dy++)                              \
        pf[i * 2 + dy] = *(const float2*)(xp + dy * 256 + 2 * (lane + 32 * i));   \
} while (0)

#define LOAD_W(ck) do {                                                           \
    const float4* wp = (const float4*)(g_W + (ck) * 6144);                        \
    _Pragma("unroll") for (int i = 0; i < 6; i++) wpf[i] = wp[tid + 256 * i];     \
} while (0)

__global__ void __launch_bounds__(256, 1)
pm_main(const float* __restrict__ x, float* __restrict__ out) {
    __shared__ float As[32 * 136];        // [k][w], stride 136 (=8 mod 32): conflict-free frags
    __shared__ float Ws[192 * 36];        // [n][k], stride 36 (=4 mod 32): conflict-free frags
    __shared__ float ssum_s[128], ssq_s[128], smu[128], srr[128];
    __shared__ float ss[192], st[192];

    const int tid = threadIdx.x, lane = tid & 31, wid = tid >> 5;
    const int gid = lane >> 2, l4 = lane & 3;
    const int c_local = wid;
    const int warp_m = wid >> 2, warp_n = wid & 3;
    const int h = blockIdx.x, b = blockIdx.y;

    if (tid < 128) { ssum_s[tid] = 0.f; ssq_s[tid] = 0.f; }
    if (tid < 192) { ss[tid] = g_s[tid]; st[tid] = g_t[tid]; }

    float acc[4][6][4];
    #pragma unroll
    for (int i = 0; i < 4; i++)
    #pragma unroll
    for (int j = 0; j < 6; j++)
    #pragma unroll
    for (int q = 0; q < 4; q++) acc[i][j][q] = 0.f;

    float2 pf[8];
    float4 wpf[6];
    float ssum[4] = {0, 0, 0, 0}, ssq[4] = {0, 0, 0, 0};

    const size_t xbase0 = (((size_t)b * 96) * 256 + 2 * h) * 256;

    LOAD_A(0); LOAD_W(0);

    #pragma unroll 1
    for (int ck = 0; ck < 12; ++ck) {
        __syncthreads();
        // ---- STS A (f32 -> tf32) + LN stats from raw values ----
        #pragma unroll
        for (int i = 0; i < 4; i++) {
            int w = lane + 32 * i;
            #pragma unroll
            for (int dy = 0; dy < 2; dy++) {
                float2 v = pf[i * 2 + dy];
                int k0 = c_local * 4 + dy * 2;
                As[k0 * 136 + w]       = tf32r(v.x);
                As[(k0 + 1) * 136 + w] = tf32r(v.y);
                ssq[i] += v.x * v.x + v.y * v.y;
                if (dy == 0) ssum[i] += v.x;
            }
        }
        // ---- STS W ----
        #pragma unroll
        for (int i = 0; i < 6; i++) {
            int j = tid + 256 * i;
            *(float4*)&Ws[(j >> 3) * 36 + (j & 7) * 4] = wpf[i];
        }
        __syncthreads();
        if (ck < 11) { LOAD_A(ck + 1); LOAD_W(ck + 1); }  // prefetch overlaps mma
        // ---- mma: 4 k-steps of 8 ----
        #pragma unroll
        for (int s = 0; s < 4; s++) {
            uint32_t a0[4], a1[4], a2[4], a3[4], b0[6], b1[6];
            #pragma unroll
            for (int mt = 0; mt < 4; mt++) {
                const float* ap = As + (8 * s + l4) * 136 + warp_m * 64 + mt * 16 + gid;
                a0[mt] = __float_as_uint(ap[0]);
                a1[mt] = __float_as_uint(ap[8]);
                a2[mt] = __float_as_uint(ap[4 * 136]);
                a3[mt] = __float_as_uint(ap[4 * 136 + 8]);
            }
            #pragma unroll
            for (int nt = 0; nt < 6; nt++) {
                const float* bp = Ws + (warp_n * 48 + nt * 8 + gid) * 36 + 8 * s + l4;
                b0[nt] = __float_as_uint(bp[0]);
                b1[nt] = __float_as_uint(bp[4]);
            }
            #pragma unroll
            for (int mt = 0; mt < 4; mt++)
            #pragma unroll
            for (int nt = 0; nt < 6; nt++) {
                asm volatile(
                    "mma.sync.aligned.m16n8k8.row.col.f32.tf32.tf32.f32 "
                    "{%0,%1,%2,%3}, {%4,%5,%6,%7}, {%8,%9}, {%0,%1,%2,%3};"
                    : "+f"(acc[mt][nt][0]), "+f"(acc[mt][nt][1]),
                      "+f"(acc[mt][nt][2]), "+f"(acc[mt][nt][3])
                    : "r"(a0[mt]), "r"(a1[mt]), "r"(a2[mt]), "r"(a3[mt]),
                      "r"(b0[nt]), "r"(b1[nt]));
            }
        }
    }

    // ---- LN stats reduce (8 c-partials per w) ----
    #pragma unroll
    for (int i = 0; i < 4; i++) {
        atomicAdd(&ssum_s[lane + 32 * i], ssum[i]);
        atomicAdd(&ssq_s[lane + 32 * i],  ssq[i]);
    }
    __syncthreads();
    if (tid < 128) {
        float mu  = ssum_s[tid] * (1.f / 192.f);
        float var = ssq_s[tid] * (1.f / 384.f) - mu * mu;
        smu[tid] = mu;
        srr[tid] = rsqrtf(var + 1e-5f);
    }
    __syncthreads();

    // ---- fused epilogue ----
    float* ob = out + ((size_t)b * 16384 + (size_t)h * 128) * 192;
    #pragma unroll
    for (int mt = 0; mt < 4; mt++) {
        #pragma unroll
        for (int hf = 0; hf < 2; hf++) {
            int m = warp_m * 64 + mt * 16 + gid + 8 * hf;
            float mu = smu[m], r = srr[m];
            #pragma unroll
            for (int nt = 0; nt < 6; nt++) {
                int d = warp_n * 48 + nt * 8 + l4 * 2;
                float v0 = r * (acc[mt][nt][2 * hf]     - mu * ss[d])     + st[d];
                float v1 = r * (acc[mt][nt][2 * hf + 1] - mu * ss[d + 1]) + st[d + 1];
                *(float2*)(ob + (size_t)m * 192 + d) = make_float2(v0, v1);
            }
        }
    }
}

extern "C" void kernel_launch(void* const* d_in, const int* in_sizes, int n_in,
                              void* d_out, int out_size) {
    const float* x  = (const float*)d_in[0];
    const float* nw = (const float*)d_in[1];
    const float* nb = (const float*)d_in[2];
    const float* wr = (const float*)d_in[3];
    float* out = (float*)d_out;
    (void)in_sizes; (void)n_in; (void)out_size;

    pm_prep_w<<<288, 256>>>(nw, wr);
    pm_prep_st<<<1, 192>>>(nw, nb, wr);
    pm_main<<<dim3(128, 16), 256>>>(x, out);
}

// round 6
// speedup vs baseline: 1.6387x; 1.6387x over previous
#include <cuda_runtime.h>
#include <cuda_fp16.h>
#include <cstdint>

// PatchMerged fused: Haar-DWT2 + LayerNorm + (384->192) GEMM, fp16 mma.sync.
// out[b, l, d] = r*(G - mu*s[d]) + t[d],  G = patch @ W4
//   mu = sum_c x[b,c,2h,2w]/192 ; var = sum_patch x^2/384 - mu^2  (Haar identities)

__device__ __align__(16) __half g_Wh[12 * 6144];  // 12 k-chunks, pre-swizzled [96r x 128B]
__device__ float2 g_st2[192];                     // (s,t) folded reduction vectors

// ---- prep: fold Haar + LN-gamma into W4, emit swizzled fp16 chunk images ----
__global__ void pm_prep_w(const float* __restrict__ nw, const float* __restrict__ wr) {
    int idx = blockIdx.x * 256 + threadIdx.x;
    if (idx >= 384 * 192) return;
    int kg = idx / 192, d = idx - kg * 192;
    int c = kg >> 2, q = kg & 3, dy = q >> 1, dx = q & 1;
    float wll = nw[c]       * wr[c * 192 + d];
    float wlh = nw[96 + c]  * wr[(96 + c) * 192 + d];
    float whl = nw[192 + c] * wr[(192 + c) * 192 + d];
    float whh = nw[288 + c] * wr[(288 + c) * 192 + d];
    float v = 0.5f * (wll + (dy ? -wlh : wlh) + (dx ? -whl : whl)
                          + ((dx ^ dy) ? -whh : whh));
    int ck = c >> 3, kl = ((c & 7) << 2) | q;      // chunk, k-local 0..31
    int r = d >> 1;
    int off = r * 128 + (d & 1) * 64 + (((kl >> 3) ^ (r & 3)) << 4) + (kl & 7) * 2;
    g_Wh[ck * 6144 + (off >> 1)] = __float2half_rn(v);
}

__global__ void pm_prep_st(const float* __restrict__ nw, const float* __restrict__ nb,
                           const float* __restrict__ wr) {
    int d = threadIdx.x;
    if (d >= 192) return;
    float s = 0.f, t = 0.f;
    for (int yc = 0; yc < 384; ++yc) {
        float w = wr[yc * 192 + d];
        s += nw[yc] * w; t += nb[yc] * w;
    }
    g_st2[d] = make_float2(s, t);
}

__device__ __forceinline__ uint32_t smem_u32(const void* p) {
    uint32_t a;
    asm("{ .reg .u64 t; cvta.to.shared.u64 t, %1; cvt.u32.u64 %0, t; }" : "=r"(a) : "l"(p));
    return a;
}
// swizzled byte offset into a [rows/2][128B] tile (2 logical rows per 128B line,
// 4x16B granules per 64B row segment, granule XOR-swizzled by row for
// conflict-free STS.128 and LDS.32 fragment access)
__device__ __forceinline__ int sw_off(int row, int k) {
    int r = row >> 1;
    return r * 128 + (row & 1) * 64 + (((k >> 3) ^ (r & 3)) << 4) + (k & 7) * 2;
}

#define LOADX(ck) do {                                                                 \
    _Pragma("unroll") for (int ci = 0; ci < 2; ci++)                                   \
    _Pragma("unroll") for (int dy = 0; dy < 2; dy++)                                   \
        pf[ci][dy] = *(const float2*)(x +                                              \
            (((size_t)b * 96 + (ck) * 8 + 2 * cp + ci) * 256 + 2 * h + dy) * 256       \
            + 2 * (w0 + wh * 32 + lane));                                              \
} while (0)

__global__ void __launch_bounds__(256, 2)
pm_main(const float* __restrict__ x, float* __restrict__ out) {
    __shared__ __align__(16) char sA[4096];    // 64 rows x 32 k fp16, swizzled
    __shared__ __align__(16) char sB[12288];   // 192 rows x 32 k fp16, swizzled
    __shared__ float ssum_s[64], ssq_s[64], smu[64], srr[64];

    const int tid = threadIdx.x, lane = tid & 31, wid = tid >> 5;
    const int gid = lane >> 2, t4 = lane & 3;
    const int cp = wid & 3, wh = wid >> 2;     // warp = (channel-pair, w-half)
    const int h = blockIdx.x >> 1, w0 = (blockIdx.x & 1) * 64, b = blockIdx.y;
    const int wloc = wh * 32 + lane;

    const uint32_t sbA = smem_u32(sA), sbB = smem_u32(sB);

    if (tid < 64) { ssum_s[tid] = 0.f; ssq_s[tid] = 0.f; }

    float acc[2][6][4];
    #pragma unroll
    for (int i = 0; i < 2; i++)
    #pragma unroll
    for (int j = 0; j < 6; j++)
    #pragma unroll
    for (int q = 0; q < 4; q++) acc[i][j][q] = 0.f;

    float2 pf[2][2];
    float ssum_t = 0.f, ssq_t = 0.f;
    LOADX(0);

    // store address for this thread's 16B quad: rows {2h,2h+1} x chans {2cp,2cp+1}
    // at row=wloc, k = 8*cp .. 8*cp+7  ->  granule = cp ^ ((wloc>>1)&3)
    const uint32_t a_st = sbA + (uint32_t)((wloc >> 1) * 128 + (wloc & 1) * 64
                                 + ((cp ^ ((wloc >> 1) & 3)) << 4));

    #pragma unroll 1
    for (int ck = 0; ck < 12; ++ck) {
        __syncthreads();   // prev chunk fully consumed
        // stage B chunk via cp.async (L2-resident pre-swizzled image)
        {
            const char* gsrc = (const char*)g_Wh + ck * 12288 + tid * 16;
            unsigned long long g0 = (unsigned long long)__cvta_generic_to_global(gsrc);
            #pragma unroll
            for (int i = 0; i < 3; i++)
                asm volatile("cp.async.cg.shared.global [%0], [%1], 16;"
                             :: "r"(sbB + tid * 16 + i * 4096), "l"(g0 + i * 4096) : "memory");
            asm volatile("cp.async.commit_group;" ::: "memory");
        }
        // A: stats (raw f32) + fp16 convert + one swizzled 16B store (conflict-free)
        {
            float2 v00 = pf[0][0], v01 = pf[0][1], v10 = pf[1][0], v11 = pf[1][1];
            ssum_t += v00.x + v10.x;
            ssq_t  += v00.x * v00.x + v00.y * v00.y + v01.x * v01.x + v01.y * v01.y
                    + v10.x * v10.x + v10.y * v10.y + v11.x * v11.x + v11.y * v11.y;
            __half2 h0 = __floats2half2_rn(v00.x, v00.y);
            __half2 h1 = __floats2half2_rn(v01.x, v01.y);
            __half2 h2 = __floats2half2_rn(v10.x, v10.y);
            __half2 h3 = __floats2half2_rn(v11.x, v11.y);
            asm volatile("st.shared.v4.b32 [%0], {%1,%2,%3,%4};"
                         :: "r"(a_st),
                            "r"(*(uint32_t*)&h0), "r"(*(uint32_t*)&h1),
                            "r"(*(uint32_t*)&h2), "r"(*(uint32_t*)&h3) : "memory");
        }
        asm volatile("cp.async.wait_group 0;" ::: "memory");
        __syncthreads();   // A + B ready
        if (ck < 11) LOADX(ck + 1);   // LDG issues overlap the MMAs below

        #pragma unroll
        for (int s = 0; s < 2; s++) {
            uint32_t ua[2][4], ub[6][2];
            #pragma unroll
            for (int mt = 0; mt < 2; mt++)
            #pragma unroll
            for (int kh = 0; kh < 2; kh++)
            #pragma unroll
            for (int rh = 0; rh < 2; rh++) {
                int row = wh * 32 + mt * 16 + gid + rh * 8;
                int k = s * 16 + 2 * t4 + kh * 8;
                ua[mt][kh * 2 + rh] = *(const uint32_t*)(sA + sw_off(row, k));
            }
            #pragma unroll
            for (int nt = 0; nt < 6; nt++)
            #pragma unroll
            for (int kh = 0; kh < 2; kh++) {
                int n = cp * 48 + nt * 8 + gid;
                int k = s * 16 + 2 * t4 + kh * 8;
                ub[nt][kh] = *(const uint32_t*)(sB + sw_off(n, k));
            }
            #pragma unroll
            for (int mt = 0; mt < 2; mt++)
            #pragma unroll
            for (int nt = 0; nt < 6; nt++)
                asm volatile(
                    "mma.sync.aligned.m16n8k16.row.col.f32.f16.f16.f32 "
                    "{%0,%1,%2,%3}, {%4,%5,%6,%7}, {%8,%9}, {%0,%1,%2,%3};"
                    : "+f"(acc[mt][nt][0]), "+f"(acc[mt][nt][1]),
                      "+f"(acc[mt][nt][2]), "+f"(acc[mt][nt][3])
                    : "r"(ua[mt][0]), "r"(ua[mt][1]), "r"(ua[mt][2]), "r"(ua[mt][3]),
                      "r"(ub[nt][0]), "r"(ub[nt][1]));
        }
    }

    // ---- LN stats reduce (4 channel-pair partials per row) ----
    atomicAdd(&ssum_s[wloc], ssum_t);
    atomicAdd(&ssq_s[wloc],  ssq_t);
    __syncthreads();
    if (tid < 64) {
        float mu  = ssum_s[tid] * (1.f / 192.f);
        float var = ssq_s[tid] * (1.f / 384.f) - mu * mu;
        smu[tid] = mu;
        srr[tid] = rsqrtf(var + 1e-5f);
    }
    __syncthreads();

    // ---- fused epilogue from register accumulators ----
    float* ob = out + ((size_t)b * 16384 + (size_t)h * 128 + w0) * 192;
    #pragma unroll
    for (int mt = 0; mt < 2; mt++) {
        int row0 = wh * 32 + mt * 16 + gid;
        float mu0 = smu[row0],     r0 = srr[row0];
        float mu1 = smu[row0 + 8], r1 = srr[row0 + 8];
        #pragma unroll
        for (int nt = 0; nt < 6; nt++) {
            int cb = cp * 48 + nt * 8 + 2 * t4;
            float2 st0 = __ldg(&g_st2[cb]);
            float2 st1 = __ldg(&g_st2[cb + 1]);
            float2 v0, v1;
            v0.x = r0 * (acc[mt][nt][0] - mu0 * st0.x) + st0.y;
            v0.y = r0 * (acc[mt][nt][1] - mu0 * st1.x) + st1.y;
            v1.x = r1 * (acc[mt][nt][2] - mu1 * st0.x) + st0.y;
            v1.y = r1 * (acc[mt][nt][3] - mu1 * st1.x) + st1.y;
            *(float2*)(ob + (size_t)row0 * 192 + cb)       = v0;
            *(float2*)(ob + (size_t)(row0 + 8) * 192 + cb) = v1;
        }
    }
}

extern "C" void kernel_launch(void* const* d_in, const int* in_sizes, int n_in,
                              void* d_out, int out_size) {
    const float* x  = (const float*)d_in[0];
    const float* nw = (const float*)d_in[1];
    const float* nb = (const float*)d_in[2];
    const float* wr = (const float*)d_in[3];
    float* out = (float*)d_out;
    (void)in_sizes; (void)n_in; (void)out_size;

    pm_prep_w<<<288, 256>>>(nw, wr);
    pm_prep_st<<<1, 192>>>(nw, nb, wr);
    pm_main<<<dim3(256, 16), 256>>>(x, out);
}

// round 7
// speedup vs baseline: 2.5220x; 1.5391x over previous
#include <cuda_runtime.h>
#include <cuda_fp16.h>
#include <cstdint>

// PatchMerged fused: Haar-DWT2 + LayerNorm + (384->192) GEMM, fp16 mma.sync.
// Persistent CTAs, full weight matrix resident in SMEM, M-tile = 128 pixels.
// out[b, l, d] = r*(G - mu*s[d]) + t[d],  G = patch @ W4
//   mu = sum_c x[b,c,2h,2w]/192 ; var = sum_patch x^2/384 - mu^2  (Haar identities)

__device__ __align__(16) __half g_Wh[73728];   // 6 chunks x [192 n-rows x 64 k] swizzled
__device__ float2 g_st2[192];                  // (s,t) folded reduction vectors
__device__ int g_tilectr;

__global__ void pm_reset() { g_tilectr = 0; }

// ---- prep: fold Haar + LN-gamma into W4, emit swizzled fp16 chunk images ----
__global__ void pm_prep_w(const float* __restrict__ nw, const float* __restrict__ wr) {
    int idx = blockIdx.x * 256 + threadIdx.x;
    if (idx >= 384 * 192) return;
    int kg = idx / 192, d = idx - kg * 192;
    int c = kg >> 2, q = kg & 3, dy = q >> 1, dx = q & 1;
    float wll = nw[c]       * wr[c * 192 + d];
    float wlh = nw[96 + c]  * wr[(96 + c) * 192 + d];
    float whl = nw[192 + c] * wr[(192 + c) * 192 + d];
    float whh = nw[288 + c] * wr[(288 + c) * 192 + d];
    float v = 0.5f * (wll + (dy ? -wlh : wlh) + (dx ? -whl : whl)
                          + ((dx ^ dy) ? -whh : whh));
    int ck = c >> 4, kl = ((c & 15) << 2) | q;       // chunk 0..5, k-local 0..63
    int off = ck * 24576 + d * 128 + ((((kl >> 3) ^ (d & 7)) << 4)) + (kl & 7) * 2;
    g_Wh[off >> 1] = __float2half_rn(v);
}

__global__ void pm_prep_st(const float* __restrict__ nw, const float* __restrict__ nb,
                           const float* __restrict__ wr) {
    int d = threadIdx.x;
    if (d >= 192) return;
    float s = 0.f, t = 0.f;
    for (int yc = 0; yc < 384; ++yc) {
        float w = wr[yc * 192 + d];
        s += nw[yc] * w; t += nb[yc] * w;
    }
    g_st2[d] = make_float2(s, t);
}

__device__ __forceinline__ uint32_t smem_u32(const void* p) {
    uint32_t a;
    asm("{ .reg .u64 t; cvta.to.shared.u64 t, %1; cvt.u32.u64 %0, t; }" : "=r"(a) : "l"(p));
    return a;
}

// SMEM map (dynamic, 189568 B): W | A double-buffer | red | mu | rr | ctr
static constexpr int SM_W   = 0;         // 147456
static constexpr int SM_A   = 147456;    // 2 x 16384 (128 rows x 64 k fp16, swizzled)
static constexpr int SM_RED = 180224;    // 8x128 sums, then 8x128 ssq (8192 B)
static constexpr int SM_MU  = 188416;    // 128 f32
static constexpr int SM_RR  = 188928;    // 128 f32
static constexpr int SM_CTR = 189440;
static constexpr int SMEM_SZ = 189568;

// per-chunk x load: warp wid owns channels {16ck+2wid, +1}; lanes x j cover 128 pixels
#define LDGX(ck) do {                                                                  \
    _Pragma("unroll") for (int ci = 0; ci < 2; ci++)                                   \
    _Pragma("unroll") for (int dy = 0; dy < 2; dy++)                                   \
    _Pragma("unroll") for (int j = 0; j < 4; j++)                                      \
        pf[ci][dy][j] = *(const float2*)(x +                                           \
            (((size_t)b * 96 + (ck) * 16 + 2 * wid + ci) * 256 + 2 * h + dy) * 256     \
            + 2 * (lane + 32 * j));                                                    \
} while (0)

__global__ void __launch_bounds__(256, 1)
pm_main(const float* __restrict__ x, float* __restrict__ out) {
    extern __shared__ char smem[];
    const uint32_t sb = smem_u32(smem);
    const int tid = threadIdx.x, lane = tid & 31, wid = tid >> 5;
    const int gid = lane >> 2, t4 = lane & 3;
    const int wh = wid >> 2, cp = wid & 3;    // MMA warp grid: 2 (M) x 4 (N)

    // ---- stage full weight matrix into SMEM (once per CTA) ----
    {
        unsigned long long g0 =
            (unsigned long long)__cvta_generic_to_global((const char*)g_Wh + tid * 16);
        #pragma unroll
        for (int i = 0; i < 36; i++)
            asm volatile("cp.async.cg.shared.global [%0], [%1], 16;"
                         :: "r"(sb + SM_W + tid * 16 + i * 4096),
                            "l"(g0 + (unsigned long long)i * 4096) : "memory");
        asm volatile("cp.async.commit_group;" ::: "memory");
        asm volatile("cp.async.wait_group 0;" ::: "memory");
    }
    __syncthreads();

    float2 pf[2][2][4];

    for (;;) {
        // ---- steal a tile ----
        if (tid == 0) *(int*)(smem + SM_CTR) = atomicAdd(&g_tilectr, 1);
        __syncthreads();
        const int t = *(int*)(smem + SM_CTR);
        if (t >= 2048) break;
        const int b = t >> 7, h = t & 127;

        float acc[4][6][4];
        #pragma unroll
        for (int i = 0; i < 4; i++)
        #pragma unroll
        for (int j = 0; j < 6; j++)
        #pragma unroll
        for (int q = 0; q < 4; q++) acc[i][j][q] = 0.f;
        float ssum_t[4] = {0, 0, 0, 0}, ssq_t[4] = {0, 0, 0, 0};

        LDGX(0);

        #pragma unroll 1
        for (int ck = 0; ck < 6; ++ck) {
            const uint32_t abuf = sb + SM_A + (uint32_t)((ck & 1) << 14);
            // ---- A: stats (raw f32) + fp16 convert + swizzled STS.128 ----
            #pragma unroll
            for (int j = 0; j < 4; j++) {
                const int p = lane + 32 * j;
                float2 v00 = pf[0][0][j], v01 = pf[0][1][j];
                float2 v10 = pf[1][0][j], v11 = pf[1][1][j];
                ssum_t[j] += v00.x + v10.x;
                ssq_t[j]  += v00.x * v00.x + v00.y * v00.y + v01.x * v01.x + v01.y * v01.y
                           + v10.x * v10.x + v10.y * v10.y + v11.x * v11.x + v11.y * v11.y;
                __half2 h0 = __floats2half2_rn(v00.x, v00.y);
                __half2 h1 = __floats2half2_rn(v01.x, v01.y);
                __half2 h2 = __floats2half2_rn(v10.x, v10.y);
                __half2 h3 = __floats2half2_rn(v11.x, v11.y);
                asm volatile("st.shared.v4.b32 [%0], {%1,%2,%3,%4};"
                             :: "r"(abuf + p * 128 + ((wid ^ (p & 7)) << 4)),
                                "r"(*(uint32_t*)&h0), "r"(*(uint32_t*)&h1),
                                "r"(*(uint32_t*)&h2), "r"(*(uint32_t*)&h3) : "memory");
            }
            __syncthreads();                 // A(ck) visible; also fences buffer reuse
            if (ck < 5) LDGX(ck + 1);        // DRAM latency hides under MMAs below

            const uint32_t wck = sb + SM_W + (uint32_t)(ck * 24576);
            #pragma unroll
            for (int s = 0; s < 4; s++) {
                uint32_t ua[4][4], ub[6][2];
                #pragma unroll
                for (int mt = 0; mt < 4; mt++)
                #pragma unroll
                for (int kh = 0; kh < 2; kh++)
                #pragma unroll
                for (int rh = 0; rh < 2; rh++) {
                    int row = wh * 64 + mt * 16 + gid + rh * 8;
                    int g = 2 * s + kh;
                    asm volatile("ld.shared.b32 %0, [%1];" : "=r"(ua[mt][kh * 2 + rh])
                        : "r"(abuf + row * 128 + (((g ^ (row & 7)) << 4)) + t4 * 4));
                }
                #pragma unroll
                for (int nt = 0; nt < 6; nt++)
                #pragma unroll
                for (int kh = 0; kh < 2; kh++) {
                    int n = cp * 48 + nt * 8 + gid;
                    int g = 2 * s + kh;
                    asm volatile("ld.shared.b32 %0, [%1];" : "=r"(ub[nt][kh])
                        : "r"(wck + n * 128 + (((g ^ (n & 7)) << 4)) + t4 * 4));
                }
                #pragma unroll
                for (int mt = 0; mt < 4; mt++)
                #pragma unroll
                for (int nt = 0; nt < 6; nt++)
                    asm volatile(
                        "mma.sync.aligned.m16n8k16.row.col.f32.f16.f16.f32 "
                        "{%0,%1,%2,%3}, {%4,%5,%6,%7}, {%8,%9}, {%0,%1,%2,%3};"
                        : "+f"(acc[mt][nt][0]), "+f"(acc[mt][nt][1]),
                          "+f"(acc[mt][nt][2]), "+f"(acc[mt][nt][3])
                        : "r"(ua[mt][0]), "r"(ua[mt][1]), "r"(ua[mt][2]), "r"(ua[mt][3]),
                          "r"(ub[nt][0]), "r"(ub[nt][1]));
            }
        }

        // ---- LN stats: per-(warp,pixel) partials -> mu, 1/sigma ----
        #pragma unroll
        for (int j = 0; j < 4; j++) {
            int p = lane + 32 * j;
            *(float*)(smem + SM_RED + (wid * 128 + p) * 4)        = ssum_t[j];
            *(float*)(smem + SM_RED + 4096 + (wid * 128 + p) * 4) = ssq_t[j];
        }
        __syncthreads();
        if (tid < 128) {
            float s = 0.f, qq = 0.f;
            #pragma unroll
            for (int w = 0; w < 8; w++) {
                s  += *(float*)(smem + SM_RED + (w * 128 + tid) * 4);
                qq += *(float*)(smem + SM_RED + 4096 + (w * 128 + tid) * 4);
            }
            float mu = s * (1.f / 192.f);
            float var = qq * (1.f / 384.f) - mu * mu;
            *(float*)(smem + SM_MU + tid * 4) = mu;
            *(float*)(smem + SM_RR + tid * 4) = rsqrtf(var + 1e-5f);
        }
        __syncthreads();

        // ---- fused epilogue from register accumulators ----
        float* ob = out + ((size_t)b * 16384 + (size_t)h * 128) * 192;
        #pragma unroll
        for (int mt = 0; mt < 4; mt++) {
            int row0 = wh * 64 + mt * 16 + gid;
            float mu0 = *(float*)(smem + SM_MU + row0 * 4);
            float r0  = *(float*)(smem + SM_RR + row0 * 4);
            float mu1 = *(float*)(smem + SM_MU + (row0 + 8) * 4);
            float r1  = *(float*)(smem + SM_RR + (row0 + 8) * 4);
            #pragma unroll
            for (int nt = 0; nt < 6; nt++) {
                int cb = cp * 48 + nt * 8 + 2 * t4;
                float2 st0 = __ldg(&g_st2[cb]);
                float2 st1 = __ldg(&g_st2[cb + 1]);
                float2 v0, v1;
                v0.x = r0 * (acc[mt][nt][0] - mu0 * st0.x) + st0.y;
                v0.y = r0 * (acc[mt][nt][1] - mu0 * st1.x) + st1.y;
                v1.x = r1 * (acc[mt][nt][2] - mu1 * st0.x) + st0.y;
                v1.y = r1 * (acc[mt][nt][3] - mu1 * st1.x) + st1.y;
                *(float2*)(ob + (size_t)row0 * 192 + cb)       = v0;
                *(float2*)(ob + (size_t)(row0 + 8) * 192 + cb) = v1;
            }
        }
    }
}

extern "C" void kernel_launch(void* const* d_in, const int* in_sizes, int n_in,
                              void* d_out, int out_size) {
    const float* x  = (const float*)d_in[0];
    const float* nw = (const float*)d_in[1];
    const float* nb = (const float*)d_in[2];
    const float* wr = (const float*)d_in[3];
    float* out = (float*)d_out;
    (void)in_sizes; (void)n_in; (void)out_size;

    static int cfg = 0;
    if (!cfg) {
        cudaFuncSetAttribute(pm_main, cudaFuncAttributeMaxDynamicSharedMemorySize, SMEM_SZ);
        cfg = 1;
    }
    pm_prep_w<<<288, 256>>>(nw, wr);
    pm_prep_st<<<1, 192>>>(nw, nb, wr);
    pm_reset<<<1, 1>>>();
    pm_main<<<160, 256, SMEM_SZ>>>(x, out);
}

// round 9
// speedup vs baseline: 2.7449x; 1.0884x over previous
#include <cuda_runtime.h>
#include <cuda_fp16.h>
#include <cstdint>

// PatchMerged fused: Haar-DWT2 + LayerNorm + (384->192) GEMM, fp16 mma.sync.
// Persistent CTAs, full weight matrix resident in SMEM, M-tile = 128 pixels,
// ldmatrix fragment loads.
// out[b, l, d] = r*(G - mu*s[d]) + t[d],  G = patch @ W4
//   mu = sum_c x[b,c,2h,2w]/192 ; var = sum_patch x^2/384 - mu^2  (Haar identities)

__device__ __align__(16) __half g_Wh[73728];   // 6 chunks x [192 n-rows x 64 k] swizzled
__device__ float2 g_st2[192];                  // (s,t) folded reduction vectors
__device__ int g_tilectr;

// ---- prep: fold Haar + LN-gamma into W4, emit swizzled fp16 chunk images ----
__global__ void pm_prep_w(const float* __restrict__ nw, const float* __restrict__ wr) {
    int idx = blockIdx.x * 256 + threadIdx.x;
    if (idx >= 384 * 192) return;
    int kg = idx / 192, d = idx - kg * 192;
    int c = kg >> 2, q = kg & 3, dy = q >> 1, dx = q & 1;
    float wll = nw[c]       * wr[c * 192 + d];
    float wlh = nw[96 + c]  * wr[(96 + c) * 192 + d];
    float whl = nw[192 + c] * wr[(192 + c) * 192 + d];
    float whh = nw[288 + c] * wr[(288 + c) * 192 + d];
    float v = 0.5f * (wll + (dy ? -wlh : wlh) + (dx ? -whl : whl)
                          + ((dx ^ dy) ? -whh : whh));
    int ck = c >> 4, kl = ((c & 15) << 2) | q;       // chunk 0..5, k-local 0..63
    int off = ck * 24576 + d * 128 + ((((kl >> 3) ^ (d & 7)) << 4)) + (kl & 7) * 2;
    g_Wh[off >> 1] = __float2half_rn(v);
}

// grid 192 x 128 threads: block = one output channel d; also resets tile counter
__global__ void pm_prep_st(const float* __restrict__ nw, const float* __restrict__ nb,
                           const float* __restrict__ wr) {
    __shared__ float rs[4], rt[4];
    const int d = blockIdx.x, tid = threadIdx.x;
    float s = 0.f, t = 0.f;
    for (int yc = tid; yc < 384; yc += 128) {
        float w = wr[yc * 192 + d];
        s += nw[yc] * w; t += nb[yc] * w;
    }
    #pragma unroll
    for (int o = 16; o > 0; o >>= 1) {
        s += __shfl_down_sync(0xffffffffu, s, o);
        t += __shfl_down_sync(0xffffffffu, t, o);
    }
    if ((tid & 31) == 0) { rs[tid >> 5] = s; rt[tid >> 5] = t; }
    __syncthreads();
    if (tid == 0) {
        g_st2[d] = make_float2(rs[0] + rs[1] + rs[2] + rs[3],
                               rt[0] + rt[1] + rt[2] + rt[3]);
        if (d == 0) g_tilectr = 0;
    }
}

__device__ __forceinline__ uint32_t smem_u32(const void* p) {
    uint32_t a;
    asm("{ .reg .u64 t; cvta.to.shared.u64 t, %1; cvt.u32.u64 %0, t; }" : "=r"(a) : "l"(p));
    return a;
}

// SMEM map (dynamic, 189568 B): W | A double-buffer | red | mu | rr | ctr
static constexpr int SM_W   = 0;         // 147456
static constexpr int SM_A   = 147456;    // 2 x 16384 (128 rows x 64 k fp16, swizzled)
static constexpr int SM_RED = 180224;    // 8x128 sums, then 8x128 ssq (8192 B)
static constexpr int SM_MU  = 188416;    // 128 f32
static constexpr int SM_RR  = 188928;    // 128 f32
static constexpr int SM_CTR = 189440;
static constexpr int SMEM_SZ = 189568;

// per-chunk x load: warp wid owns channels {16ck+2wid, +1}; lanes x j cover 128 pixels
#define LDGX(ck) do {                                                                  \
    _Pragma("unroll") for (int ci = 0; ci < 2; ci++)                                   \
    _Pragma("unroll") for (int dy = 0; dy < 2; dy++)                                   \
    _Pragma("unroll") for (int j = 0; j < 4; j++)                                      \
        pf[ci][dy][j] = *(const float2*)(x +                                           \
            (((size_t)b * 96 + (ck) * 16 + 2 * wid + ci) * 256 + 2 * h + dy) * 256     \
            + 2 * (lane + 32 * j));                                                    \
} while (0)

__global__ void __launch_bounds__(256, 1)
pm_main(const float* __restrict__ x, float* __restrict__ out) {
    extern __shared__ char smem[];
    const uint32_t sb = smem_u32(smem);
    const int tid = threadIdx.x, lane = tid & 31, wid = tid >> 5;
    const int gid = lane >> 2, t4 = lane & 3;
    const int wh = wid >> 2, cp = wid & 3;    // MMA warp grid: 2 (M) x 4 (N)
    const int l7 = lane & 7;

    // ldmatrix per-lane row-offset bases (tile select via lane bits 3,4)
    //   A tiles: (r,k0),(r+8,k0),(r,k8),(r+8,k8):  +8 rows on bit3, +k8 on bit4
    //   B tiles: (n,k0),(n,k8),(n+8,k0),(n+8,k8):  +k8 on bit3, +8 rows on bit4
    const uint32_t arow_off = (uint32_t)((wh * 64 + l7 + ((lane >> 3) & 1) * 8) * 128);
    const uint32_t brow_off = (uint32_t)((cp * 48 + l7 + (lane >> 4) * 8) * 128);
    const int ga_sel = lane >> 4;          // A k-granule bit
    const int gb_sel = (lane >> 3) & 1;    // B k-granule bit

    // ---- stage full weight matrix into SMEM (once per CTA) ----
    {
        unsigned long long g0 =
            (unsigned long long)__cvta_generic_to_global((const char*)g_Wh + tid * 16);
        #pragma unroll
        for (int i = 0; i < 36; i++)
            asm volatile("cp.async.cg.shared.global [%0], [%1], 16;"
                         :: "r"(sb + SM_W + tid * 16 + i * 4096),
                            "l"(g0 + (unsigned long long)i * 4096) : "memory");
        asm volatile("cp.async.commit_group;" ::: "memory");
        asm volatile("cp.async.wait_group 0;" ::: "memory");
    }
    __syncthreads();

    float2 pf[2][2][4];

    for (;;) {
        // ---- steal a tile ----
        if (tid == 0) *(int*)(smem + SM_CTR) = atomicAdd(&g_tilectr, 1);
        __syncthreads();
        const int t = *(int*)(smem + SM_CTR);
        if (t >= 2048) break;
        const int b = t >> 7, h = t & 127;

        float acc[4][6][4];
        #pragma unroll
        for (int i = 0; i < 4; i++)
        #pragma unroll
        for (int j = 0; j < 6; j++)
        #pragma unroll
        for (int q = 0; q < 4; q++) acc[i][j][q] = 0.f;
        float ssum_t[4] = {0, 0, 0, 0}, ssq_t[4] = {0, 0, 0, 0};

        LDGX(0);

        #pragma unroll 1
        for (int ck = 0; ck < 6; ++ck) {
            const uint32_t abuf = sb + SM_A + (uint32_t)((ck & 1) << 14);
            // ---- A: stats (raw f32) + fp16 convert + swizzled STS.128 ----
            #pragma unroll
            for (int j = 0; j < 4; j++) {
                const int p = lane + 32 * j;
                float2 v00 = pf[0][0][j], v01 = pf[0][1][j];
                float2 v10 = pf[1][0][j], v11 = pf[1][1][j];
                ssum_t[j] += v00.x + v10.x;
                ssq_t[j]  += v00.x * v00.x + v00.y * v00.y + v01.x * v01.x + v01.y * v01.y
                           + v10.x * v10.x + v10.y * v10.y + v11.x * v11.x + v11.y * v11.y;
                __half2 h0 = __floats2half2_rn(v00.x, v00.y);
                __half2 h1 = __floats2half2_rn(v01.x, v01.y);
                __half2 h2 = __floats2half2_rn(v10.x, v10.y);
                __half2 h3 = __floats2half2_rn(v11.x, v11.y);
                asm volatile("st.shared.v4.b32 [%0], {%1,%2,%3,%4};"
                             :: "r"(abuf + p * 128 + ((wid ^ (p & 7)) << 4)),
                                "r"(*(uint32_t*)&h0), "r"(*(uint32_t*)&h1),
                                "r"(*(uint32_t*)&h2), "r"(*(uint32_t*)&h3) : "memory");
            }
            __syncthreads();                 // A(ck) visible; also fences buffer reuse
            if (ck < 5) LDGX(ck + 1);        // DRAM latency hides under MMAs below

            const uint32_t wck = sb + SM_W + (uint32_t)(ck * 24576);
            #pragma unroll
            for (int s = 0; s < 4; s++) {
                uint32_t ua[4][4], ub[6][2];
                const uint32_t xa = (uint32_t)((((2 * s + ga_sel) ^ l7)) << 4);
                const uint32_t xb = (uint32_t)((((2 * s + gb_sel) ^ l7)) << 4);
                #pragma unroll
                for (int mt = 0; mt < 4; mt++)
                    asm volatile(
                        "ldmatrix.sync.aligned.m8n8.x4.shared.b16 {%0,%1,%2,%3}, [%4];"
                        : "=r"(ua[mt][0]), "=r"(ua[mt][1]),
                          "=r"(ua[mt][2]), "=r"(ua[mt][3])
                        : "r"(abuf + arow_off + mt * 2048 + xa));
                #pragma unroll
                for (int p = 0; p < 3; p++)
                    asm volatile(
                        "ldmatrix.sync.aligned.m8n8.x4.shared.b16 {%0,%1,%2,%3}, [%4];"
                        : "=r"(ub[2 * p][0]), "=r"(ub[2 * p][1]),
                          "=r"(ub[2 * p + 1][0]), "=r"(ub[2 * p + 1][1])
                        : "r"(wck + brow_off + p * 2048 + xb));
                #pragma unroll
                for (int mt = 0; mt < 4; mt++)
                #pragma unroll
                for (int nt = 0; nt < 6; nt++)
                    asm volatile(
                        "mma.sync.aligned.m16n8k16.row.col.f32.f16.f16.f32 "
                        "{%0,%1,%2,%3}, {%4,%5,%6,%7}, {%8,%9}, {%0,%1,%2,%3};"
                        : "+f"(acc[mt][nt][0]), "+f"(acc[mt][nt][1]),
                          "+f"(acc[mt][nt][2]), "+f"(acc[mt][nt][3])
                        : "r"(ua[mt][0]), "r"(ua[mt][1]), "r"(ua[mt][2]), "r"(ua[mt][3]),
                          "r"(ub[nt][0]), "r"(ub[nt][1]));
            }
        }

        // ---- LN stats: per-(warp,pixel) partials -> mu, 1/sigma ----
        #pragma unroll
        for (int j = 0; j < 4; j++) {
            int p = lane + 32 * j;
            *(float*)(smem + SM_RED + (wid * 128 + p) * 4)        = ssum_t[j];
            *(float*)(smem + SM_RED + 4096 + (wid * 128 + p) * 4) = ssq_t[j];
        }
        __syncthreads();
        if (tid < 128) {
            float s = 0.f, qq = 0.f;
            #pragma unroll
            for (int w = 0; w < 8; w++) {
                s  += *(float*)(smem + SM_RED + (w * 128 + tid) * 4);
                qq += *(float*)(smem + SM_RED + 4096 + (w * 128 + tid) * 4);
            }
            float mu = s * (1.f / 192.f);
            float var = qq * (1.f / 384.f) - mu * mu;
            *(float*)(smem + SM_MU + tid * 4) = mu;
            *(float*)(smem + SM_RR + tid * 4) = rsqrtf(var + 1e-5f);
        }
        __syncthreads();

        // ---- fused epilogue from register accumulators ----
        float* ob = out + ((size_t)b * 16384 + (size_t)h * 128) * 192;
        #pragma unroll
        for (int mt = 0; mt < 4; mt++) {
            int row0 = wh * 64 + mt * 16 + gid;
            float mu0 = *(float*)(smem + SM_MU + row0 * 4);
            float r0  = *(float*)(smem + SM_RR + row0 * 4);
            float mu1 = *(float*)(smem + SM_MU + (row0 + 8) * 4);
            float r1  = *(float*)(smem + SM_RR + (row0 + 8) * 4);
            #pragma unroll
            for (int nt = 0; nt < 6; nt++) {
                int cb = cp * 48 + nt * 8 + 2 * t4;
                float2 st0 = __ldg(&g_st2[cb]);
                float2 st1 = __ldg(&g_st2[cb + 1]);
                float2 v0, v1;
                v0.x = r0 * (acc[mt][nt][0] - mu0 * st0.x) + st0.y;
                v0.y = r0 * (acc[mt][nt][1] - mu0 * st1.x) + st1.y;
                v1.x = r1 * (acc[mt][nt][2] - mu1 * st0.x) + st0.y;
                v1.y = r1 * (acc[mt][nt][3] - mu1 * st1.x) + st1.y;
                *(float2*)(ob + (size_t)row0 * 192 + cb)       = v0;
                *(float2*)(ob + (size_t)(row0 + 8) * 192 + cb) = v1;
            }
        }
    }
}

extern "C" void kernel_launch(void* const* d_in, const int* in_sizes, int n_in,
                              void* d_out, int out_size) {
    const float* x  = (const float*)d_in[0];
    const float* nw = (const float*)d_in[1];
    const float* nb = (const float*)d_in[2];
    const float* wr = (const float*)d_in[3];
    float* out = (float*)d_out;
    (void)in_sizes; (void)n_in; (void)out_size;

    static int cfg = 0;
    if (!cfg) {
        cudaFuncSetAttribute(pm_main, cudaFuncAttributeMaxDynamicSharedMemorySize, SMEM_SZ);
        cfg = 1;
    }
    pm_prep_w<<<288, 256>>>(nw, wr);
    pm_prep_st<<<192, 128>>>(nw, nb, wr);
    pm_main<<<160, 256, SMEM_SZ>>>(x, out);
}